// round 1
// baseline (speedup 1.0000x reference)
#include <cuda_runtime.h>

// Problem constants (from reference)
#define BB 512
#define LL 100
#define DLEN 100000
#define MARGIN 1.0f
#define GAMMA 0.9f

__device__ float g_per_label[LL];

// One block per label l. 512 threads, one batch-row i per thread.
// per_label[l] = sum_{i:pos} (up_new*S_all - ua_new*S_pos)/ua_new^2 / (n_pos*B)
__global__ __launch_bounds__(BB) void map_loss_kernel(
    const float* __restrict__ y_pred,   // (B, L)
    const float* __restrict__ y_true,   // (B, L)
    const int*   __restrict__ index,    // (B,)
    const float* __restrict__ u_all,    // (L, DLEN)
    const float* __restrict__ u_pos)    // (L, DLEN)
{
    __shared__ float s_fp[BB];
    __shared__ float s_fpp[BB + 8];   // compacted positive fp values (+pad)
    __shared__ float s_red[BB];
    __shared__ int   s_wcnt[BB / 32];

    const int l    = blockIdx.x;
    const int i    = threadIdx.x;
    const int warp = i >> 5;
    const int lane = i & 31;

    const float fp_i  = y_pred[i * LL + l];
    const bool  pos_i = (y_true[i * LL + l] == 1.0f);
    s_fp[i] = fp_i;

    // Deterministic compaction of positive fp values (row order preserved).
    unsigned m = __ballot_sync(0xffffffffu, pos_i);
    if (lane == 0) s_wcnt[warp] = __popc(m);
    __syncthreads();

    int base = 0, total = 0;
#pragma unroll
    for (int w = 0; w < BB / 32; w++) {
        int c = s_wcnt[w];
        if (w < warp) base += c;
        total += c;
    }
    if (pos_i) {
        int off = base + __popc(m & ((1u << lane) - 1u));
        s_fpp[off] = fp_i;
    }
    const int n_pos     = total;
    const int n_pos_pad = (n_pos + 7) & ~7;
    if (i < n_pos_pad - n_pos) s_fpp[n_pos + i] = -1e30f;  // pad -> relu()=0
    __syncthreads();

    const float c = MARGIN - fp_i;

    // S_all = sum_j relu(c + fp_j)^2 over all 512 j
    float A0 = 0.f, A1 = 0.f, A2 = 0.f, A3 = 0.f;
    const float4* fp4 = reinterpret_cast<const float4*>(s_fp);
#pragma unroll 4
    for (int j = 0; j < BB / 4; j++) {
        float4 v = fp4[j];
        float d0 = fmaxf(c + v.x, 0.0f);
        float d1 = fmaxf(c + v.y, 0.0f);
        float d2 = fmaxf(c + v.z, 0.0f);
        float d3 = fmaxf(c + v.w, 0.0f);
        A0 = fmaf(d0, d0, A0);
        A1 = fmaf(d1, d1, A1);
        A2 = fmaf(d2, d2, A2);
        A3 = fmaf(d3, d3, A3);
    }
    const float S_all = (A0 + A1) + (A2 + A3);

    // S_pos = sum over compacted positive j only
    float P0 = 0.f, P1 = 0.f, P2 = 0.f, P3 = 0.f;
    const float4* fpp4 = reinterpret_cast<const float4*>(s_fpp);
    const int np4 = n_pos_pad >> 2;
#pragma unroll 4
    for (int j = 0; j < np4; j++) {
        float4 v = fpp4[j];
        float d0 = fmaxf(c + v.x, 0.0f);
        float d1 = fmaxf(c + v.y, 0.0f);
        float d2 = fmaxf(c + v.z, 0.0f);
        float d3 = fmaxf(c + v.w, 0.0f);
        P0 = fmaf(d0, d0, P0);
        P1 = fmaf(d1, d1, P1);
        P2 = fmaf(d2, d2, P2);
        P3 = fmaf(d3, d3, P3);
    }
    const float S_pos = (P0 + P1) + (P2 + P3);

    float contrib = 0.0f;
    if (pos_i) {
        const int   idx = index[i];
        const float ua  = u_all[(long long)l * DLEN + idx];
        const float up  = u_pos[(long long)l * DLEN + idx];
        const float row_mean     = S_all * (1.0f / (float)BB);
        const float pos_row_mean = S_pos * (1.0f / (float)BB);
        const float ua_new = (1.0f - GAMMA) * ua + GAMMA * row_mean;
        const float up_new = (1.0f - GAMMA) * up + GAMMA * pos_row_mean;
        contrib = (up_new * S_all - ua_new * S_pos) / (ua_new * ua_new);
    }

    // Block reduction of contributions (fixed order -> deterministic)
    s_red[i] = contrib;
    __syncthreads();
#pragma unroll
    for (int s = BB / 2; s > 32; s >>= 1) {
        if (i < s) s_red[i] += s_red[i + s];
        __syncthreads();
    }
    if (i < 32) {
        float v = s_red[i] + s_red[i + 32];
#pragma unroll
        for (int off = 16; off > 0; off >>= 1)
            v += __shfl_down_sync(0xffffffffu, v, off);
        if (i == 0)
            g_per_label[l] = v / ((float)n_pos * (float)BB);
    }
}

__global__ void final_reduce_kernel(float* __restrict__ out) {
    const int t = threadIdx.x;  // 32 threads
    float v = 0.0f;
    for (int l = t; l < LL; l += 32) v += g_per_label[l];
#pragma unroll
    for (int off = 16; off > 0; off >>= 1)
        v += __shfl_down_sync(0xffffffffu, v, off);
    if (t == 0) out[0] = v / (float)LL;
}

extern "C" void kernel_launch(void* const* d_in, const int* in_sizes, int n_in,
                              void* d_out, int out_size) {
    const float* y_pred = (const float*)d_in[0];
    const float* y_true = (const float*)d_in[1];
    const int*   index  = (const int*)d_in[2];
    const float* u_all  = (const float*)d_in[3];
    const float* u_pos  = (const float*)d_in[4];
    float* out = (float*)d_out;

    map_loss_kernel<<<LL, BB>>>(y_pred, y_true, index, u_all, u_pos);
    final_reduce_kernel<<<1, 32>>>(out);
}

// round 3
// speedup vs baseline: 1.1830x; 1.1830x over previous
#include <cuda_runtime.h>

#define BB 512
#define LL 100
#define DLEN 100000
#define GAMMA 0.9f

__device__ float g_per_label[LL];
__device__ unsigned int g_cnt = 0;

// Single fused kernel. One block per label, 512 threads.
// Only positive rows contribute. Compacted positives are processed with
// 2 threads per row (j-range split) when 2*n_pos <= 512.
// ALL warp collectives are executed unconditionally (no divergent sync).
__global__ __launch_bounds__(BB) void map_loss_fused_kernel(
    const float* __restrict__ y_pred,   // (B, L)
    const float* __restrict__ y_true,   // (B, L)
    const int*   __restrict__ index,    // (B,)
    const float* __restrict__ u_all,    // (L, DLEN)
    const float* __restrict__ u_pos,    // (L, DLEN)
    float* __restrict__ out)
{
    __shared__ float s_fp[BB];
    __shared__ float s_fpp[BB + 8];     // compacted positive fp (+pad)
    __shared__ int   s_prow[BB];        // original row of each positive
    __shared__ float s_red[BB];
    __shared__ int   s_wcnt[BB / 32];
    __shared__ int   s_last;

    const int l    = blockIdx.x;
    const int t    = threadIdx.x;
    const int warp = t >> 5;
    const int lane = t & 31;

    const float fp_i  = y_pred[t * LL + l];
    const bool  pos_i = (y_true[t * LL + l] == 1.0f);
    s_fp[t]  = fp_i;
    s_fpp[t] = -1e30f;                  // full init: safe clamped reads later
    if (t < 8) s_fpp[BB + t] = -1e30f;

    // Deterministic compaction of positive rows (row order preserved)
    unsigned m = __ballot_sync(0xffffffffu, pos_i);
    if (lane == 0) s_wcnt[warp] = __popc(m);
    __syncthreads();

    int base = 0, total = 0;
#pragma unroll
    for (int w = 0; w < BB / 32; w++) {
        int c = s_wcnt[w];
        if (w < warp) base += c;
        total += c;
    }
    if (pos_i) {
        int off = base + __popc(m & ((1u << lane) - 1u));
        s_fpp[off]  = fp_i;
        s_prow[off] = t;
    }
    const int n_pos     = total;
    const int n_pos_pad = (n_pos + 7) & ~7;
    __syncthreads();

    // Work assignment (all block-uniform decisions):
    const bool split2 = (2 * n_pos <= BB);
    const int  K      = split2 ? 2 : 1;
    const bool active = t < n_pos * K;
    const int  p      = split2 ? (t >> 1) : t;   // positive-row slot (always < BB)
    const int  half   = split2 ? (t & 1) : 0;

    // Prefetch ua/up gathers early so DRAM latency hides under the fma loops.
    float ua = 0.f, up = 0.f;
    if (active && half == 0) {
        const int idx = index[s_prow[p]];
        ua = u_all[(long long)l * DLEN + idx];
        up = u_pos[(long long)l * DLEN + idx];
    }

    // Inactive threads: c = -1e30 -> every relu is 0 -> S_all = S_pos = 0.
    const float c = active ? (1.0f - s_fpp[p]) : -1e30f;

    // ---- S_all over all 512 fp values, this thread's half of j ----
    const float4* fp4 = reinterpret_cast<const float4*>(s_fp);
    const int a_len = split2 ? (BB / 8) : (BB / 4);
    const int a_beg = half * (BB / 8);
    float A0 = 0.f, A1 = 0.f, A2 = 0.f, A3 = 0.f;
#pragma unroll 4
    for (int j = a_beg; j < a_beg + a_len; j++) {
        float4 v = fp4[j];
        float d0 = fmaxf(c + v.x, 0.0f);
        float d1 = fmaxf(c + v.y, 0.0f);
        float d2 = fmaxf(c + v.z, 0.0f);
        float d3 = fmaxf(c + v.w, 0.0f);
        A0 = fmaf(d0, d0, A0);
        A1 = fmaf(d1, d1, A1);
        A2 = fmaf(d2, d2, A2);
        A3 = fmaf(d3, d3, A3);
    }
    float S_all = (A0 + A1) + (A2 + A3);

    // ---- S_pos over compacted positives (pad entries give relu 0) ----
    const float4* fpp4 = reinterpret_cast<const float4*>(s_fpp);
    const int np4 = n_pos_pad >> 2;       // multiple of 2
    int pb, pe;
    if (split2) { int h = np4 >> 1; pb = half * h; pe = pb + h; }
    else        { pb = 0; pe = np4; }
    float P0 = 0.f, P1 = 0.f, P2 = 0.f, P3 = 0.f;
#pragma unroll 4
    for (int j = pb; j < pe; j++) {
        float4 v = fpp4[j];
        float d0 = fmaxf(c + v.x, 0.0f);
        float d1 = fmaxf(c + v.y, 0.0f);
        float d2 = fmaxf(c + v.z, 0.0f);
        float d3 = fmaxf(c + v.w, 0.0f);
        P0 = fmaf(d0, d0, P0);
        P1 = fmaf(d1, d1, P1);
        P2 = fmaf(d2, d2, P2);
        P3 = fmaf(d3, d3, P3);
    }
    float S_pos = (P0 + P1) + (P2 + P3);

    // Combine halves — executed by ALL threads (warp-uniform, no deadlock).
    // Inactive threads' partners contribute 0; result discarded anyway.
    if (split2) {
        S_all += __shfl_xor_sync(0xffffffffu, S_all, 1);
        S_pos += __shfl_xor_sync(0xffffffffu, S_pos, 1);
    }

    float contrib = 0.0f;
    if (active && half == 0) {
        const float row_mean     = S_all * (1.0f / (float)BB);
        const float pos_row_mean = S_pos * (1.0f / (float)BB);
        const float ua_new = (1.0f - GAMMA) * ua + GAMMA * row_mean;
        const float up_new = (1.0f - GAMMA) * up + GAMMA * pos_row_mean;
        contrib = (up_new * S_all - ua_new * S_pos) / (ua_new * ua_new);
    }

    // Block reduction (fixed order -> deterministic)
    s_red[t] = contrib;
    __syncthreads();
#pragma unroll
    for (int s = BB / 2; s > 32; s >>= 1) {
        if (t < s) s_red[t] += s_red[t + s];
        __syncthreads();
    }
    if (t < 32) {
        float v = s_red[t] + s_red[t + 32];
#pragma unroll
        for (int off = 16; off > 0; off >>= 1)
            v += __shfl_down_sync(0xffffffffu, v, off);
        if (t == 0) {
            g_per_label[l] = v / ((float)n_pos * (float)BB);
            __threadfence();
            unsigned old = atomicAdd(&g_cnt, 1u);
            s_last = (old == LL - 1) ? 1 : 0;
        }
    }
    __syncthreads();

    // Last block folds the per-label values in fixed order (deterministic).
    if (s_last && t == 0) {
        __threadfence();
        float acc = 0.0f;
        volatile float* gp = g_per_label;
#pragma unroll
        for (int j = 0; j < LL; j++) acc += gp[j];
        out[0] = acc / (float)LL;
        g_cnt = 0;   // reset for next graph replay
    }
}

extern "C" void kernel_launch(void* const* d_in, const int* in_sizes, int n_in,
                              void* d_out, int out_size) {
    const float* y_pred = (const float*)d_in[0];
    const float* y_true = (const float*)d_in[1];
    const int*   index  = (const int*)d_in[2];
    const float* u_all  = (const float*)d_in[3];
    const float* u_pos  = (const float*)d_in[4];
    float* out = (float*)d_out;

    map_loss_fused_kernel<<<LL, BB>>>(y_pred, y_true, index, u_all, u_pos, out);
}